// round 4
// baseline (speedup 1.0000x reference)
#include <cuda_runtime.h>
#include <cuda_bf16.h>
#include <math.h>

// Problem constants
#define B_   8
#define MB_  512
#define IN_  1024
#define EMB_ 1024
#define H_   16
#define KVH_ 4
#define HD_  64
#define BS_  16
#define KW_  32          // K_HISTORY window
#define NJ_  288         // 256 score cols + 32 value-proj cols
#define MTOT (B_*MB_)    // 4096

// score scale: 1/sqrt(64) * log2(e)  (scores kept in log2 domain -> ex2 in k4)
#define SCORE_SCALE 0.1803368801111204f

// Device scratch
__device__ float g_qT[HD_*256];          // [d][j = h*16+q]  (roped, transposed)
__device__ float g_WoR[EMB_*2];          // [f][c]
__device__ float g_Wcomb[IN_*NJ_];       // [e][j]
__device__ float g_P[MTOT*NJ_];          // [b*512+t][j]

// ---------------------------------------------------------------------------
// packed fp32x2 helpers (Blackwell FFMA2 pipe)
// ---------------------------------------------------------------------------
__device__ __forceinline__ void ffma2(unsigned long long& d,
                                      unsigned long long a,
                                      unsigned long long b) {
    asm("fma.rn.f32x2 %0, %1, %2, %0;" : "+l"(d) : "l"(a), "l"(b));
}
__device__ __forceinline__ unsigned long long splat2(float x) {
    unsigned long long r;
    asm("mov.b64 %0, {%1, %1};" : "=l"(r) : "r"(__float_as_int(x)));
    return r;
}
__device__ __forceinline__ float ex2f(float x) {
    float r;
    asm("ex2.approx.ftz.f32 %0, %1;" : "=f"(r) : "f"(x));
    return r;
}
__device__ __forceinline__ float rcpf(float x) {
    float r;
    asm("rcp.approx.ftz.f32 %0, %1;" : "=f"(r) : "f"(x));
    return r;
}

// ---------------------------------------------------------------------------
// K1: blocks [0,64):   q = RoPE(output_queries @ Wq) -> g_qT (transposed)
//     blocks [64,320): WoR = Wo @ Wr  (warp per output row)
// 128 threads per block.
// ---------------------------------------------------------------------------
__global__ __launch_bounds__(128)
void k1_prep(const float* __restrict__ oq,   // (16,1024)
             const float* __restrict__ Wq,   // (1024,1024)
             const float* __restrict__ fc,   // (512,64)
             const float* __restrict__ fs,   // (512,64)
             const float* __restrict__ Wo,   // (1024,1024)
             const float* __restrict__ Wr)   // (1024,2)
{
    int bid = blockIdx.x;
    int tid = threadIdx.x;
    if (bid < 64) {
        // q projection: block = (qq, cg). covers cols [cg*256, cg*256+256)
        int qq = bid >> 2;
        int cg = bid & 3;
        __shared__ __align__(16) float oqs[EMB_];
        __shared__ __align__(16) float rawS[256];
        for (int i = tid; i < EMB_; i += 128) oqs[i] = oq[qq*EMB_ + i];
        __syncthreads();

        int c0 = cg*256 + tid*2;
        unsigned long long acc[8];
        #pragma unroll
        for (int i = 0; i < 8; i++) acc[i] = 0ULL;
        const float* wbase = Wq + c0;
        #pragma unroll 1
        for (int e = 0; e < EMB_; e += 8) {
            #pragma unroll
            for (int u = 0; u < 8; u++) {
                unsigned long long w2 =
                    *(const unsigned long long*)(wbase + (size_t)(e+u)*EMB_);
                ffma2(acc[u], w2, splat2(oqs[e+u]));
            }
        }
        float rx = 0.f, ry = 0.f;
        #pragma unroll
        for (int i = 0; i < 8; i++) {
            float2 v = *(float2*)&acc[i];
            rx += v.x; ry += v.y;
        }
        rawS[tid*2 + 0] = rx;
        rawS[tid*2 + 1] = ry;
        __syncthreads();

        #pragma unroll
        for (int t = 0; t < 2; t++) {
            int lc  = tid*2 + t;
            int col = cg*256 + lc;
            int hh  = col >> 6;
            int d   = col & 63;
            int lp  = (lc & ~63) | ((d < 32) ? d + 32 : d - 32);
            float rh = (d < 32) ? -rawS[lp] : rawS[lp];
            float val = rawS[lc] * fc[qq*HD_ + d] + rh * fs[qq*HD_ + d];
            g_qT[d*256 + hh*BS_ + qq] = val;
        }
    } else {
        // WoR: warp per row e
        __shared__ __align__(16) float Wrs[EMB_*2];
        for (int i = tid; i < EMB_*2; i += 128) Wrs[i] = Wr[i];
        __syncthreads();
        int w    = tid >> 5;
        int lane = tid & 31;
        int e = (bid - 64)*4 + w;
        const float* wor = Wo + (size_t)e * EMB_;
        float p0 = 0.f, p1 = 0.f;
        #pragma unroll 4
        for (int i = 0; i < 32; i++) {
            int f = i*32 + lane;
            float wv = wor[f];
            float2 r = *(const float2*)&Wrs[f*2];
            p0 += wv * r.x;
            p1 += wv * r.y;
        }
        #pragma unroll
        for (int off = 16; off > 0; off >>= 1) {
            p0 += __shfl_xor_sync(0xffffffff, p0, off);
            p1 += __shfl_xor_sync(0xffffffff, p1, off);
        }
        if (lane == 0) {
            g_WoR[e*2 + 0] = p0;
            g_WoR[e*2 + 1] = p1;
        }
    }
}

// ---------------------------------------------------------------------------
// K2: combined projection weights, 8 e-rows per block, 288 threads.
//   j <  256: scores col = (Wk[e,kv*64+d] . qT) * SCORE_SCALE
//   j >= 256: value col  = (Wv[e,kv*64+d] . WoR)
// g_qT reads are coalesced (j contiguous across warp).
// ---------------------------------------------------------------------------
#define E_PER 8
__global__ __launch_bounds__(288)
void k2_wcomb(const float* __restrict__ Wk,   // (1024,256)
              const float* __restrict__ Wv)   // (1024,256)
{
    __shared__ __align__(16) float wks[E_PER*256];
    __shared__ __align__(16) float wvs[E_PER*256];
    __shared__ __align__(16) float WoRs[16*130];  // [h*130 + d*2 + c], conflict-free
    int e0  = blockIdx.x * E_PER;
    int tid = threadIdx.x;

    for (int idx = tid; idx < E_PER*256; idx += 288) {
        int e = idx >> 8, jj = idx & 255;
        wks[idx] = Wk[(size_t)(e0+e)*256 + jj];
        wvs[idx] = Wv[(size_t)(e0+e)*256 + jj];
    }
    for (int idx = tid; idx < 2048; idx += 288) {
        int f = idx >> 1, c = idx & 1;
        int hh = f >> 6, d = f & 63;
        WoRs[hh*130 + d*2 + c] = g_WoR[idx];
    }
    __syncthreads();

    int j = tid;
    float s[E_PER];
    #pragma unroll
    for (int e = 0; e < E_PER; e++) s[e] = 0.f;

    if (j < 256) {
        int hh = j >> 4;
        int kv = hh >> 2;
        const float* qcol = g_qT + j;
        #pragma unroll 4
        for (int d = 0; d < HD_; d++) {
            float qd = qcol[d*256];           // coalesced across warp
            #pragma unroll
            for (int e = 0; e < E_PER; e++)
                s[e] += wks[e*256 + kv*HD_ + d] * qd;   // broadcast LDS
        }
        #pragma unroll
        for (int e = 0; e < E_PER; e++)
            g_Wcomb[(size_t)(e0+e)*NJ_ + j] = s[e] * SCORE_SCALE;
    } else {
        int j2 = j - 256;
        int hh = j2 >> 1;
        int c  = j2 & 1;
        int kv = hh >> 2;
        #pragma unroll 4
        for (int d = 0; d < HD_; d++) {
            float wv = WoRs[hh*130 + d*2 + c];
            #pragma unroll
            for (int e = 0; e < E_PER; e++)
                s[e] += wvs[e*256 + kv*HD_ + d] * wv;
        }
        #pragma unroll
        for (int e = 0; e < E_PER; e++)
            g_Wcomb[(size_t)(e0+e)*NJ_ + j] = s[e];
    }
}

// ---------------------------------------------------------------------------
// K3: P = h (4096x1024) @ Wcomb (1024x288)
// BM=256 BN=32 BK=32, 256 threads, grid (16,9)=144 (one wave). FFMA2 pipe.
// ---------------------------------------------------------------------------
#define BM 256
#define BN 32
#define BK 32
#define ASTR 258
#define BSTR 34

__global__ __launch_bounds__(256, 1)
void k3_gemm(const float* __restrict__ A)  // h as (4096,1024)
{
    __shared__ __align__(16) float As[BK * ASTR];   // As[k*ASTR + m]
    __shared__ __align__(16) float Bs[BK * BSTR];   // Bs[k*BSTR + n]
    const int m0 = blockIdx.x * BM;
    const int n0 = blockIdx.y * BN;
    const int tid = threadIdx.x;
    const int lk = tid & 31;
    const int lm = tid >> 5;
    const int tn = tid & 15;
    const int tm = tid >> 4;

    unsigned long long acc[8][2];
    #pragma unroll
    for (int j = 0; j < 8; j++) { acc[j][0] = 0ULL; acc[j][1] = 0ULL; }

    const float* Abase = A + (size_t)(m0 + lm) * IN_ + lk;
    const float* Bbase = g_Wcomb + (size_t)lm * NJ_ + n0 + lk;

    float ra[32];
    float rb[4];
    #pragma unroll
    for (int i = 0; i < 32; i++) ra[i] = Abase[(size_t)(8*i) * IN_];
    #pragma unroll
    for (int i = 0; i < 4; i++)  rb[i] = Bbase[(size_t)(8*i) * NJ_];

    const int NIT = IN_ / BK;   // 32
    for (int it = 0; it < NIT; it++) {
        #pragma unroll
        for (int i = 0; i < 32; i++) As[lk*ASTR + lm + 8*i] = ra[i];
        #pragma unroll
        for (int i = 0; i < 4; i++)  Bs[(lm + 8*i)*BSTR + lk] = rb[i];
        __syncthreads();

        if (it + 1 < NIT) {
            int k0 = (it + 1) * BK;
            #pragma unroll
            for (int i = 0; i < 32; i++) ra[i] = Abase[(size_t)(8*i) * IN_ + k0];
            #pragma unroll
            for (int i = 0; i < 4; i++)  rb[i] = Bbase[(size_t)(k0 + 8*i) * NJ_];
        }

        #pragma unroll
        for (int k = 0; k < BK; k++) {
            const float* arow = As + k*ASTR + tm*16;
            float2 b = *(const float2*)(Bs + k*BSTR + tn*2);
            unsigned long long b0 = splat2(b.x);
            unsigned long long b1 = splat2(b.y);
            #pragma unroll
            for (int j = 0; j < 8; j++) {
                unsigned long long a2 = *(const unsigned long long*)(arow + 2*j);
                ffma2(acc[j][0], a2, b0);
                ffma2(acc[j][1], a2, b1);
            }
        }
        __syncthreads();
    }

    #pragma unroll
    for (int j = 0; j < 8; j++) {
        int r = m0 + tm*16 + 2*j;
        #pragma unroll
        for (int n = 0; n < 2; n++) {
            float2 v = *(float2*)&acc[j][n];
            int cc = n0 + tn*2 + n;
            g_P[(size_t)r * NJ_ + cc]     = v.x;
            g_P[(size_t)(r+1) * NJ_ + cc] = v.y;
        }
    }
}

// ---------------------------------------------------------------------------
// K4: windowed softmax-attention + 2-col output.
// 256 threads: (hg, ml, q). ex2 hoisted into the staging pass (8x MUFU reuse).
// Scores arrive in log2 domain (SCORE_SCALE folded log2e); padded rows get
// v=0 -> 2^0 = 1 = exp(0), exactly matching the reference's zero-pad softmax.
// ---------------------------------------------------------------------------
#define MT 8
#define ROWS (MT + KW_ - 1)   // 39
#define SSTR 272              // stride: (r*16+col) banks -> conflict-free

__global__ __launch_bounds__(256)
void k4_attn(const float* __restrict__ br, float* __restrict__ out)
{
    __shared__ __align__(16) float Es[ROWS * SSTR];   // 2^score, 42.4KB
    __shared__ __align__(16) float Pvs[ROWS][32];     // value-proj cols (broadcast reads)
    int bx = blockIdx.x;
    int b  = bx >> 6;
    int m0 = (bx & 63) * MT;
    int tid = threadIdx.x;

    // stage: exponentiate score cols, copy value cols
    for (int idx = tid; idx < ROWS * NJ_; idx += 256) {
        int r = idx / NJ_;
        int j = idx - r * NJ_;
        int g = m0 - (KW_-1) + r;
        float v = 0.f;
        if (g >= 0) v = g_P[((size_t)(b*MB_ + g))*NJ_ + j];
        if (j < 256) Es[r*SSTR + j] = ex2f(v);
        else         Pvs[r][j-256] = v;
    }
    __syncthreads();

    int q  = tid & 15;
    int ml = (tid >> 4) & 7;
    int hg = tid >> 7;           // 0/1: handles h in [hg*8, hg*8+8)
    float o0 = 0.f, o1 = 0.f;

    #pragma unroll 1
    for (int hi = 0; hi < 8; hi++) {
        int hh  = hg*8 + hi;
        int col = hh*16 + q;
        float sum = 0.f, a0 = 0.f, a1 = 0.f;
        #pragma unroll
        for (int k = 0; k < KW_; k++) {
            float w = Es[(ml + k)*SSTR + col];
            float2 pv = *(const float2*)&Pvs[ml + k][2*hh];
            sum += w;
            a0 += w * pv.x;
            a1 += w * pv.y;
        }
        float inv = rcpf(sum);
        o0 += a0 * inv;
        o1 += a1 * inv;
    }

    // reduce across hg pairs (reuse Es storage; all Es reads are done)
    __syncthreads();
    float2* redv = (float2*)Es;
    redv[tid] = make_float2(o0, o1);
    __syncthreads();
    if (hg == 0) {
        float2 me = redv[tid];
        float2 ot = redv[tid + 128];
        int m = m0 + ml;
        size_t o = (((size_t)(b*MB_ + m))*BS_ + q);
        float2 res = make_float2(me.x + ot.x + br[0], me.y + ot.y + br[1]);
        *(float2*)(out + o*2) = res;
    }
}

// ---------------------------------------------------------------------------
extern "C" void kernel_launch(void* const* d_in, const int* in_sizes, int n_in,
                              void* d_out, int out_size)
{
    const float* h   = (const float*)d_in[0];   // (8,512,1024)
    const float* fc  = (const float*)d_in[1];   // (512,64)
    const float* fs  = (const float*)d_in[2];   // (512,64)
    const float* Wq  = (const float*)d_in[3];   // (1024,1024)
    const float* Wk  = (const float*)d_in[4];   // (1024,256)
    const float* Wv  = (const float*)d_in[5];   // (1024,256)
    const float* Wo  = (const float*)d_in[6];   // (1024,1024)
    const float* oq  = (const float*)d_in[7];   // (16,1024)
    const float* Wr  = (const float*)d_in[8];   // (1024,2)
    const float* br  = (const float*)d_in[9];   // (2,)
    float* out = (float*)d_out;

    k1_prep<<<320, 128>>>(oq, Wq, fc, fs, Wo, Wr);
    k2_wcomb<<<128, 288>>>(Wk, Wv);
    k3_gemm<<<dim3(16, 9), 256>>>(h);
    k4_attn<<<512, 256>>>(br, out);
}

// round 5
// speedup vs baseline: 1.8011x; 1.8011x over previous
#include <cuda_runtime.h>
#include <cuda_bf16.h>
#include <math.h>

// Problem constants
#define B_   8
#define MB_  512
#define IN_  1024
#define EMB_ 1024
#define H_   16
#define KVH_ 4
#define HD_  64
#define BS_  16
#define KW_  32
#define NJ_  288
#define MTOT (B_*MB_)      // 4096
#define GRID 148
#define NTHR 256

// 1/sqrt(64) * log2(e): scores in log2 domain -> ex2 in attention phase
#define SCORE_SCALE 0.1803368801111204f

typedef unsigned long long ull;

// Device scratch (padded apart)
__device__ float g_qT[HD_*256 + 64];     // [d][j = h*16+q]
__device__ float g_WoR[EMB_*2 + 64];     // [f][c]
__device__ float g_Wcomb[IN_*NJ_ + 64];  // [e][j]
__device__ float g_P[MTOT*NJ_ + 64];     // [b*512+t][j]

// grid barrier state (persists across launches; self-consistent)
__device__ unsigned g_bar_ctr  = 0;
__device__ unsigned g_bar_sense = 0;

// ---------------------------------------------------------------------------
__device__ __forceinline__ void ffma2(ull& d, ull a, ull b) {
    asm("fma.rn.f32x2 %0, %1, %2, %0;" : "+l"(d) : "l"(a), "l"(b));
}
__device__ __forceinline__ ull splat2(float x) {
    ull r;
    asm("mov.b64 %0, {%1, %1};" : "=l"(r) : "r"(__float_as_int(x)));
    return r;
}
__device__ __forceinline__ float ex2f(float x) {
    float r; asm("ex2.approx.ftz.f32 %0, %1;" : "=f"(r) : "f"(x)); return r;
}
__device__ __forceinline__ float rcpf(float x) {
    float r; asm("rcp.approx.ftz.f32 %0, %1;" : "=f"(r) : "f"(x)); return r;
}

// ---------------------------------------------------------------------------
// Shared memory union across phases (max member 47424 B < 48 KB)
// ---------------------------------------------------------------------------
#define ASTR 258
#define BSTR 36
#define MT 8
#define ROWS (MT + KW_ - 1)   // 39
#define SSTR 272

union SmemU {
    struct { float oqs[1024]; float red[1024]; float rawS[256]; } p0q;
    struct { float wrs[2048]; } p0w;
    struct { float wks[2048]; float wvs[2048]; float WoRs[16*130]; } p1;
    struct { float As[32*ASTR]; float Bs[32*BSTR]; } p2;
    struct { float Es[ROWS*SSTR]; float Pvs[ROWS*32]; } p3;
};

// ---------------------------------------------------------------------------
__global__ __launch_bounds__(NTHR, 1)
void mega(const float* __restrict__ hA,   // (8,512,1024)
          const float* __restrict__ fc,   // (512,64)
          const float* __restrict__ fs,   // (512,64)
          const float* __restrict__ Wq,   // (1024,1024)
          const float* __restrict__ Wk,   // (1024,256)
          const float* __restrict__ Wv,   // (1024,256)
          const float* __restrict__ Wo,   // (1024,1024)
          const float* __restrict__ oq,   // (16,1024)
          const float* __restrict__ Wr,   // (1024,2)
          const float* __restrict__ br,   // (2,)
          float* __restrict__ out)
{
    __shared__ __align__(16) SmemU u;
    __shared__ unsigned s_sense;
    const int tid = threadIdx.x;
    const int bid = blockIdx.x;
    const int wid = tid >> 5;
    const int lane = tid & 31;

    if (tid == 0) s_sense = atomicAdd(&g_bar_sense, 0u);

    // grid barrier (sense-reversing, wrap-counting, launch-safe)
    auto gbar = [&]() {
        __syncthreads();
        if (tid == 0) {
            __threadfence();
            unsigned old = atomicInc(&g_bar_ctr, GRID - 1u);
            if (old == GRID - 1u) {
                atomicAdd(&g_bar_sense, 1u);
            } else {
                unsigned spins = 0;
                while (atomicAdd(&g_bar_sense, 0u) == s_sense) {
                    if (++spins > 100000000u) break;   // fail visible, not hung
                }
            }
            s_sense++;
            __threadfence();
        }
        __syncthreads();
    };

    // =======================================================================
    // P0a: blocks [0,64): q = RoPE(oq @ Wq), stored transposed to g_qT
    //      block = (qq = bid>>2, cg = bid&3); 4-way k-split across threads.
    // P0b: blocks [64,148): WoR = Wo @ Wr, warp per row.
    // =======================================================================
    if (bid < 64) {
        const int qq = bid >> 2;
        const int cg = bid & 3;
        for (int i = tid; i < EMB_; i += NTHR) u.p0q.oqs[i] = oq[qq*EMB_ + i];
        __syncthreads();

        const int c4 = tid & 63;          // column group (4 cols)
        const int eh = tid >> 6;          // k-slice 0..3
        const int col0 = cg*256 + c4*4;
        const int e0 = eh*256;
        float4 acc4 = make_float4(0.f, 0.f, 0.f, 0.f);
        const float* wp = Wq + (size_t)e0 * EMB_ + col0;
        #pragma unroll 1
        for (int e = 0; e < 256; e += 16) {
            #pragma unroll
            for (int v = 0; v < 16; v++) {
                float4 w4 = *(const float4*)(wp + (size_t)(e+v)*EMB_);
                float ov = u.p0q.oqs[e0 + e + v];
                acc4.x += w4.x*ov; acc4.y += w4.y*ov;
                acc4.z += w4.z*ov; acc4.w += w4.w*ov;
            }
        }
        *(float4*)&u.p0q.red[eh*256 + c4*4] = acc4;
        __syncthreads();
        if (tid < 64) {
            #pragma unroll
            for (int i = 0; i < 4; i++) {
                int c = c4*4 + i;
                u.p0q.rawS[c] = u.p0q.red[c] + u.p0q.red[256+c]
                              + u.p0q.red[512+c] + u.p0q.red[768+c];
            }
        }
        __syncthreads();
        {
            int c   = tid;                 // 0..255 local col
            int col = cg*256 + c;
            int hh  = col >> 6;
            int d   = col & 63;
            int lp  = (c & ~63) | ((d < 32) ? d + 32 : d - 32);
            float rh = (d < 32) ? -u.p0q.rawS[lp] : u.p0q.rawS[lp];
            float val = u.p0q.rawS[c] * fc[qq*HD_ + d] + rh * fs[qq*HD_ + d];
            g_qT[d*256 + hh*BS_ + qq] = val;
        }
    } else {
        for (int i = tid; i < 2048; i += NTHR) u.p0w.wrs[i] = Wr[i];
        __syncthreads();
        int gw = (bid - 64)*8 + wid;       // 0..671
        #pragma unroll
        for (int rep = 0; rep < 2; rep++) {
            int r = gw + rep*672;
            if (r < EMB_) {
                const float* wor = Wo + (size_t)r * EMB_;
                float p0 = 0.f, p1 = 0.f;
                #pragma unroll 4
                for (int i = 0; i < 32; i++) {
                    int f = i*32 + lane;
                    float wv = wor[f];
                    p0 += wv * u.p0w.wrs[f*2 + 0];
                    p1 += wv * u.p0w.wrs[f*2 + 1];
                }
                #pragma unroll
                for (int off = 16; off > 0; off >>= 1) {
                    p0 += __shfl_xor_sync(0xffffffff, p0, off);
                    p1 += __shfl_xor_sync(0xffffffff, p1, off);
                }
                if (lane == 0) { g_WoR[r*2+0] = p0; g_WoR[r*2+1] = p1; }
            }
        }
    }
    gbar();

    // =======================================================================
    // P1: Wcomb. blocks [0,128), 8 e-rows each.
    // =======================================================================
    if (bid < 128) {
        const int e0 = bid * 8;
        for (int idx = tid; idx < 2048; idx += NTHR) {
            int e = idx >> 8, jj = idx & 255;
            u.p1.wks[idx] = Wk[(size_t)(e0+e)*256 + jj];
            u.p1.wvs[idx] = Wv[(size_t)(e0+e)*256 + jj];
        }
        for (int idx = tid; idx < 2048; idx += NTHR) {
            int f = idx >> 1, c = idx & 1;
            int hh = f >> 6, d = f & 63;
            u.p1.WoRs[hh*130 + d*2 + c] = g_WoR[idx];
        }
        __syncthreads();

        // score cols: every thread one col
        {
            int j  = tid;
            int hh = j >> 4;
            int kv = hh >> 2;
            float s[8];
            #pragma unroll
            for (int e = 0; e < 8; e++) s[e] = 0.f;
            const float* qcol = g_qT + j;
            #pragma unroll 4
            for (int d = 0; d < HD_; d++) {
                float qd = qcol[d*256];
                #pragma unroll
                for (int e = 0; e < 8; e++)
                    s[e] += u.p1.wks[e*256 + kv*HD_ + d] * qd;
            }
            #pragma unroll
            for (int e = 0; e < 8; e++)
                g_Wcomb[(size_t)(e0+e)*NJ_ + j] = s[e] * SCORE_SCALE;
        }
        // value cols: threads 0..31
        if (tid < 32) {
            int j2 = tid;
            int hh = j2 >> 1;
            int c  = j2 & 1;
            int kv = hh >> 2;
            float s[8];
            #pragma unroll
            for (int e = 0; e < 8; e++) s[e] = 0.f;
            #pragma unroll 4
            for (int d = 0; d < HD_; d++) {
                float wv = u.p1.WoRs[hh*130 + d*2 + c];
                #pragma unroll
                for (int e = 0; e < 8; e++)
                    s[e] += u.p1.wvs[e*256 + kv*HD_ + d] * wv;
            }
            #pragma unroll
            for (int e = 0; e < 8; e++)
                g_Wcomb[(size_t)(e0+e)*NJ_ + 256 + j2] = s[e];
        }
    }
    gbar();

    // =======================================================================
    // P2: GEMM P = h (4096x1024) @ Wcomb (1024x288)
    // BM=256 BN=32 BK=32, 144 tiles, thread tile 8m x 4n, FFMA2 pipe.
    // =======================================================================
    if (bid < 144) {
        const int m0 = (bid & 15) * 256;
        const int n0 = (bid >> 4) * 32;
        const int lk = tid & 31;
        const int lm = tid >> 5;
        const int tm = tid >> 3;     // 0..31 -> rows tm*8 .. tm*8+7
        const int tn = tid & 7;      // 0..7  -> cols tn*4 .. tn*4+3

        ull acc[4][4];
        #pragma unroll
        for (int j = 0; j < 4; j++)
            #pragma unroll
            for (int c = 0; c < 4; c++) acc[j][c] = 0ULL;

        const float* Abase = hA + (size_t)(m0 + lm) * IN_ + lk;
        const float* Bbase = g_Wcomb + (size_t)lm * NJ_ + n0 + lk;

        float ra[32];
        float rb[4];
        #pragma unroll
        for (int i = 0; i < 32; i++) ra[i] = Abase[(size_t)(8*i) * IN_];
        #pragma unroll
        for (int i = 0; i < 4; i++)  rb[i] = Bbase[(size_t)(8*i) * NJ_];

        const int NIT = IN_ / 32;   // 32
        for (int it = 0; it < NIT; it++) {
            #pragma unroll
            for (int i = 0; i < 32; i++) u.p2.As[lk*ASTR + lm + 8*i] = ra[i];
            #pragma unroll
            for (int i = 0; i < 4; i++)  u.p2.Bs[(lm + 8*i)*BSTR + lk] = rb[i];
            __syncthreads();

            if (it + 1 < NIT) {
                int k0 = (it + 1) * 32;
                #pragma unroll
                for (int i = 0; i < 32; i++) ra[i] = Abase[(size_t)(8*i) * IN_ + k0];
                #pragma unroll
                for (int i = 0; i < 4; i++)  rb[i] = Bbase[(size_t)(k0 + 8*i) * NJ_];
            }

            #pragma unroll
            for (int k = 0; k < 32; k++) {
                const float* arow = u.p2.As + k*ASTR + tm*8;
                float4 b4 = *(const float4*)(u.p2.Bs + k*BSTR + tn*4);
                ull b0 = splat2(b4.x), b1 = splat2(b4.y);
                ull b2 = splat2(b4.z), b3 = splat2(b4.w);
                #pragma unroll
                for (int j = 0; j < 4; j++) {
                    ull a2 = *(const ull*)(arow + 2*j);
                    ffma2(acc[j][0], a2, b0);
                    ffma2(acc[j][1], a2, b1);
                    ffma2(acc[j][2], a2, b2);
                    ffma2(acc[j][3], a2, b3);
                }
            }
            __syncthreads();
        }

        #pragma unroll
        for (int j = 0; j < 4; j++) {
            int r = m0 + tm*8 + 2*j;
            #pragma unroll
            for (int c = 0; c < 4; c++) {
                float2 v = *(float2*)&acc[j][c];
                int cc = n0 + tn*4 + c;
                g_P[(size_t)r * NJ_ + cc]     = v.x;
                g_P[(size_t)(r+1) * NJ_ + cc] = v.y;
            }
        }
    }
    gbar();

    // =======================================================================
    // P3: windowed softmax attention + 2-col output. 512 tiles strided.
    // =======================================================================
    {
        const float br0 = br[0], br1 = br[1];
        const int q  = tid & 15;
        const int ml = (tid >> 4) & 7;
        const int hg = tid >> 7;

        for (int t = bid; t < 512; t += GRID) {
            int b  = t >> 6;
            int m0 = (t & 63) * MT;
            __syncthreads();   // protect previous tile's reduction reads

            for (int idx = tid; idx < ROWS * NJ_; idx += NTHR) {
                int r = idx / NJ_;
                int j = idx - r * NJ_;
                int g = m0 - (KW_-1) + r;
                float v = 0.f;
                if (g >= 0) v = g_P[((size_t)(b*MB_ + g))*NJ_ + j];
                if (j < 256) u.p3.Es[r*SSTR + j] = ex2f(v);
                else         u.p3.Pvs[r*32 + (j-256)] = v;
            }
            __syncthreads();

            float o0 = 0.f, o1 = 0.f;
            #pragma unroll 1
            for (int hi = 0; hi < 8; hi++) {
                int hh  = hg*8 + hi;
                int col = hh*16 + q;
                float sum = 0.f, a0 = 0.f, a1 = 0.f;
                #pragma unroll
                for (int k = 0; k < KW_; k++) {
                    float w = u.p3.Es[(ml + k)*SSTR + col];
                    float2 pv = *(const float2*)&u.p3.Pvs[(ml + k)*32 + 2*hh];
                    sum += w;
                    a0 += w * pv.x;
                    a1 += w * pv.y;
                }
                float inv = rcpf(sum);
                o0 += a0 * inv;
                o1 += a1 * inv;
            }
            __syncthreads();
            float2* redv = (float2*)u.p3.Es;
            redv[tid] = make_float2(o0, o1);
            __syncthreads();
            if (hg == 0) {
                float2 me = redv[tid];
                float2 ot = redv[tid + 128];
                int m = m0 + ml;
                size_t o = (((size_t)(b*MB_ + m))*BS_ + q);
                *(float2*)(out + o*2) =
                    make_float2(me.x + ot.x + br0, me.y + ot.y + br1);
            }
        }
    }
}

// ---------------------------------------------------------------------------
extern "C" void kernel_launch(void* const* d_in, const int* in_sizes, int n_in,
                              void* d_out, int out_size)
{
    const float* h   = (const float*)d_in[0];
    const float* fc  = (const float*)d_in[1];
    const float* fs  = (const float*)d_in[2];
    const float* Wq  = (const float*)d_in[3];
    const float* Wk  = (const float*)d_in[4];
    const float* Wv  = (const float*)d_in[5];
    const float* Wo  = (const float*)d_in[6];
    const float* oq  = (const float*)d_in[7];
    const float* Wr  = (const float*)d_in[8];
    const float* br  = (const float*)d_in[9];
    float* out = (float*)d_out;

    mega<<<GRID, NTHR>>>(h, fc, fs, Wq, Wk, Wv, Wo, oq, Wr, br, out);
}